// round 2
// baseline (speedup 1.0000x reference)
#include <cuda_runtime.h>
#include <math.h>
#include <stdint.h>

// Problem constants (fixed by dataset)
#define BB 8
#define NN 4096
#define CC 128
#define HH 256
#define KK 16
#define MM (BB * NN)   // 32768 rows

// ---------------------------------------------------------------------------
// Scratch (device globals -> .bss, no allocation in kernel_launch)
// ---------------------------------------------------------------------------
__device__ float g_asrc[MM * CC];
__device__ float g_adst[MM * CC];
__device__ float g_v[MM * CC];
__device__ float g_acc[MM * CC];
__device__ int   g_idx[MM * KK];

// ---------------------------------------------------------------------------
// Kernel 1: brute-force KNN (k=16 smallest d2, incl. self) per batch.
// d2 = sq_i + sq_j - 2*dot (reference formula). Selection-set only matters;
// softmax over neighbors is permutation invariant.
// One thread per target row; candidates streamed through shared tiles.
// ---------------------------------------------------------------------------
#define KNN_TILE 1024

__global__ void knn_kernel(const float* __restrict__ pos) {
    __shared__ float4 sp[KNN_TILE];   // 16 KB

    const int b = blockIdx.y;
    const float* posb = pos + (size_t)b * NN * 3;
    const int i = blockIdx.x * blockDim.x + threadIdx.x;

    const float pix = posb[i * 3 + 0];
    const float piy = posb[i * 3 + 1];
    const float piz = posb[i * 3 + 2];
    const float sqi = pix * pix + piy * piy + piz * piz;

    float d[KK];
    int   id[KK];
#pragma unroll
    for (int t = 0; t < KK; t++) { d[t] = 3.4e38f; id[t] = 0; }
    float mx = 3.4e38f;   // current max of the k-set
    int   ms = 0;         // its slot

    for (int tile = 0; tile < NN; tile += KNN_TILE) {
        __syncthreads();
        for (int j = threadIdx.x; j < KNN_TILE; j += blockDim.x) {
            const int gj = tile + j;
            const float x = posb[gj * 3 + 0];
            const float y = posb[gj * 3 + 1];
            const float z = posb[gj * 3 + 2];
            sp[j] = make_float4(x, y, z, x * x + y * y + z * z);
        }
        __syncthreads();

#pragma unroll 4
        for (int j = 0; j < KNN_TILE; j++) {
            const float4 pj = sp[j];
            float dot = pix * pj.x;
            dot = fmaf(piy, pj.y, dot);
            dot = fmaf(piz, pj.z, dot);
            const float d2 = fmaf(-2.0f, dot, sqi + pj.w);
            if (d2 < mx) {
                // predicated, fully-unrolled insert (keeps arrays in registers)
#pragma unroll
                for (int t = 0; t < KK; t++)
                    if (t == ms) { d[t] = d2; id[t] = tile + j; }
                mx = d[0]; ms = 0;
#pragma unroll
                for (int t = 1; t < KK; t++)
                    if (d[t] > mx) { mx = d[t]; ms = t; }
            }
        }
    }

    int* op = g_idx + ((size_t)b * NN + i) * KK;
#pragma unroll
    for (int t = 0; t < KK; t++) op[t] = id[t];
}

// ---------------------------------------------------------------------------
// GEMM core: C[M,N] = A[M,128] @ W[128,N] (+ bias)
// BM=128, BN=128, BK=8, 256 threads, 8x8 micro-tile (4+4 split halves).
// ---------------------------------------------------------------------------
template <bool BIAS>
__device__ __forceinline__ void gemm_body(
    const float* __restrict__ A, const float* __restrict__ W,
    const float* __restrict__ bias, float* __restrict__ Cout,
    int N, int bm, int bn) {
    __shared__ float As[8][128];   // transposed A tile: As[k][m]
    __shared__ float Bs[8][128];   // W tile: Bs[k][n]

    const int tid = threadIdx.x;
    const int tx = tid & 15;    // 0..15 -> column groups
    const int ty = tid >> 4;    // 0..15 -> row groups

    float acc[8][8];
#pragma unroll
    for (int u = 0; u < 8; u++)
#pragma unroll
        for (int v = 0; v < 8; v++) acc[u][v] = 0.0f;

    const int ar = tid >> 1;            // A row 0..127
    const int ac4 = (tid & 1) * 4;      // A col 0 or 4
    const int wr = tid >> 5;            // W row 0..7
    const int wc = (tid & 31) * 4;      // W col 0..124

    for (int k0 = 0; k0 < 128; k0 += 8) {
        const float4 av = *(const float4*)&A[(size_t)(bm + ar) * 128 + k0 + ac4];
        const float4 wv = *(const float4*)&W[(size_t)(k0 + wr) * N + bn + wc];
        As[ac4 + 0][ar] = av.x;
        As[ac4 + 1][ar] = av.y;
        As[ac4 + 2][ar] = av.z;
        As[ac4 + 3][ar] = av.w;
        *(float4*)&Bs[wr][wc] = wv;
        __syncthreads();

#pragma unroll
        for (int kk = 0; kk < 8; kk++) {
            float a[8], bfr[8];
            *(float4*)&a[0]   = *(const float4*)&As[kk][ty * 4];
            *(float4*)&a[4]   = *(const float4*)&As[kk][64 + ty * 4];
            *(float4*)&bfr[0] = *(const float4*)&Bs[kk][tx * 4];
            *(float4*)&bfr[4] = *(const float4*)&Bs[kk][64 + tx * 4];
#pragma unroll
            for (int u = 0; u < 8; u++)
#pragma unroll
                for (int v = 0; v < 8; v++)
                    acc[u][v] = fmaf(a[u], bfr[v], acc[u][v]);
        }
        __syncthreads();
    }

#pragma unroll
    for (int hu = 0; hu < 2; hu++) {
#pragma unroll
        for (int u = 0; u < 4; u++) {
            const int row = bm + hu * 64 + ty * 4 + u;
            float* cp = &Cout[(size_t)row * N + bn];
#pragma unroll
            for (int hv = 0; hv < 2; hv++) {
                const int colb = hv * 64 + tx * 4;
                float4 r;
                r.x = acc[hu * 4 + u][hv * 4 + 0];
                r.y = acc[hu * 4 + u][hv * 4 + 1];
                r.z = acc[hu * 4 + u][hv * 4 + 2];
                r.w = acc[hu * 4 + u][hv * 4 + 3];
                if (BIAS) {
                    r.x += bias[bn + colb + 0];
                    r.y += bias[bn + colb + 1];
                    r.z += bias[bn + colb + 2];
                    r.w += bias[bn + colb + 3];
                }
                *(float4*)&cp[colb] = r;
            }
        }
    }
}

// Fused projections: z selects {W_src->g_asrc, W_dst->g_adst, W_val->g_v}
__global__ void __launch_bounds__(256, 2)
proj_kernel(const float* __restrict__ A,
            const float* __restrict__ Wsrc, const float* __restrict__ Wdst,
            const float* __restrict__ Wval,
            float* __restrict__ Osrc, float* __restrict__ Odst,
            float* __restrict__ Oval) {
    const float* W = (blockIdx.z == 0) ? Wsrc : (blockIdx.z == 1) ? Wdst : Wval;
    float* O       = (blockIdx.z == 0) ? Osrc : (blockIdx.z == 1) ? Odst : Oval;
    gemm_body<false>(A, W, nullptr, O, CC, blockIdx.x * 128, 0);
}

__global__ void __launch_bounds__(256, 2)
out_gemm_kernel(const float* __restrict__ A, const float* __restrict__ W,
                const float* __restrict__ bias, float* __restrict__ Cout) {
    gemm_body<true>(A, W, bias, Cout, HH, blockIdx.x * 128, blockIdx.y * 128);
}

// ---------------------------------------------------------------------------
// Kernel 3: gather + per-(point,channel) softmax over 16 neighbors.
// One block (128 threads) per point; thread = channel. Softmax over the k
// axis is per-channel -> no cross-thread reduction at all.
// ---------------------------------------------------------------------------
__global__ void attn_kernel(const float* __restrict__ pos,
                            const float* __restrict__ Wpos,
                            const float* __restrict__ bpos) {
    const int b = blockIdx.y;
    const int i = blockIdx.x;
    const int c = threadIdx.x;

    __shared__ int   s_nbr[KK];
    __shared__ float s_rel[KK][3];

    const float* posb = pos + (size_t)b * NN * 3;
    if (c < KK) {
        const int j = g_idx[((size_t)b * NN + i) * KK + c];
        s_nbr[c] = j;
        s_rel[c][0] = posb[i * 3 + 0] - posb[j * 3 + 0];
        s_rel[c][1] = posb[i * 3 + 1] - posb[j * 3 + 1];
        s_rel[c][2] = posb[i * 3 + 2] - posb[j * 3 + 2];
    }
    __syncthreads();

    const float w0 = Wpos[c];
    const float w1 = Wpos[128 + c];
    const float w2 = Wpos[256 + c];
    const float bp = bpos[c];

    const float* asrc = g_asrc + (size_t)b * NN * CC;
    const float* vv   = g_v    + (size_t)b * NN * CC;
    const float adst  = g_adst[((size_t)b * NN + i) * CC + c];

    float alpha[KK], val[KK];
#pragma unroll
    for (int t = 0; t < KK; t++) {
        const int j = s_nbr[t];
        float delta = fmaf(s_rel[t][2], w2, bp);
        delta = fmaf(s_rel[t][1], w1, delta);
        delta = fmaf(s_rel[t][0], w0, delta);
        alpha[t] = adst - asrc[(size_t)j * CC + c] + delta;
        val[t]   = vv[(size_t)j * CC + c] + delta;
    }

    float m = alpha[0];
#pragma unroll
    for (int t = 1; t < KK; t++) m = fmaxf(m, alpha[t]);

    float s = 0.0f, acc = 0.0f;
#pragma unroll
    for (int t = 0; t < KK; t++) {
        const float e = expf(alpha[t] - m);
        s += e;
        acc = fmaf(e, val[t], acc);
    }
    g_acc[((size_t)b * NN + i) * CC + c] = acc / s;
}

// ---------------------------------------------------------------------------
// Launch
// ---------------------------------------------------------------------------
extern "C" void kernel_launch(void* const* d_in, const int* in_sizes, int n_in,
                              void* d_out, int out_size) {
    const float* x    = (const float*)d_in[0];
    const float* pos  = (const float*)d_in[1];
    const float* Wsrc = (const float*)d_in[2];
    const float* Wdst = (const float*)d_in[3];
    const float* Wval = (const float*)d_in[4];
    const float* Wpos = (const float*)d_in[5];
    const float* bpos = (const float*)d_in[6];
    const float* Wout = (const float*)d_in[7];
    const float* bout = (const float*)d_in[8];
    float* out = (float*)d_out;

    float *p_asrc, *p_adst, *p_v, *p_acc;
    cudaGetSymbolAddress((void**)&p_asrc, g_asrc);
    cudaGetSymbolAddress((void**)&p_adst, g_adst);
    cudaGetSymbolAddress((void**)&p_v,    g_v);
    cudaGetSymbolAddress((void**)&p_acc,  g_acc);

    // 1) KNN
    knn_kernel<<<dim3(NN / 256, BB), 256>>>(pos);

    // 2) projections: a_src, a_dst, v   (M=32768, K=128, N=128), fused over z
    proj_kernel<<<dim3(MM / 128, 1, 3), 256>>>(x, Wsrc, Wdst, Wval,
                                               p_asrc, p_adst, p_v);

    // 3) gather + softmax + weighted sum -> g_acc
    attn_kernel<<<dim3(NN, BB), 128>>>(pos, Wpos, bpos);

    // 4) output projection: out = g_acc @ W_out + b_out  (N=256)
    out_gemm_kernel<<<dim3(MM / 128, HH / 128), 256>>>(p_acc, Wout, bout, out);
}

// round 3
// speedup vs baseline: 1.2193x; 1.2193x over previous
#include <cuda_runtime.h>
#include <math.h>
#include <stdint.h>

// Problem constants (fixed by dataset)
#define BB 8
#define NN 4096
#define CC 128
#define HH 256
#define KK 16
#define MM (BB * NN)   // 32768 rows

#define KNN_SPLIT 2
#define KNN_CAND (NN / KNN_SPLIT)   // 2048 candidates per split
#define KNN_TILE 1024

// ---------------------------------------------------------------------------
// Scratch (device globals -> .bss, no allocation in kernel_launch)
// ---------------------------------------------------------------------------
__device__ float g_asrc[MM * CC];
__device__ float g_adst[MM * CC];
__device__ float g_v[MM * CC];
__device__ float g_acc[MM * CC];
__device__ int   g_idx[MM * KK];
__device__ float g_knn_d[MM * KNN_SPLIT * KK];
__device__ int   g_knn_i[MM * KNN_SPLIT * KK];

// ---------------------------------------------------------------------------
// Branch-free insert of (v, j) into a descending-sorted register array.
// Precondition: v < d[0]. Strict '<' everywhere so earlier (lower-index)
// candidates win ties, matching top_k's lowest-index tie-break.
// ---------------------------------------------------------------------------
__device__ __forceinline__ void sorted_insert16(float (&d)[KK], int (&id)[KK],
                                                float v, int j) {
    bool c_prev = true;   // d[0] > v guaranteed by caller
#pragma unroll
    for (int t = 0; t < KK - 1; t++) {
        const bool c_next = d[t + 1] > v;
        d[t]  = c_next ? d[t + 1]  : (c_prev ? v : d[t]);
        id[t] = c_next ? id[t + 1] : (c_prev ? j : id[t]);
        c_prev = c_next;
    }
    d[KK - 1]  = c_prev ? v : d[KK - 1];
    id[KK - 1] = c_prev ? j : id[KK - 1];
}

// ---------------------------------------------------------------------------
// KNN pass A: thread = (query, split half). Scans KNN_CAND candidates,
// keeps top-16 (d2, idx), writes to scratch.
// d2 = sq_i + sq_j - 2*dot (reference formula; selection set is what matters).
// ---------------------------------------------------------------------------
__global__ void __launch_bounds__(256)
knn_pass_a(const float* __restrict__ pos) {
    __shared__ float4 sp[KNN_TILE];   // 16 KB

    const int b = blockIdx.y;
    const int s = blockIdx.z;
    const float* posb = pos + (size_t)b * NN * 3;
    const int i = blockIdx.x * blockDim.x + threadIdx.x;

    const float pix = posb[i * 3 + 0];
    const float piy = posb[i * 3 + 1];
    const float piz = posb[i * 3 + 2];
    const float sqi = pix * pix + piy * piy + piz * piz;

    float d[KK];
    int   id[KK];
#pragma unroll
    for (int t = 0; t < KK; t++) { d[t] = 3.4e38f; id[t] = 0; }

    const int base = s * KNN_CAND;
    for (int tile = 0; tile < KNN_CAND; tile += KNN_TILE) {
        __syncthreads();
#pragma unroll
        for (int l = 0; l < KNN_TILE / 256; l++) {
            const int j  = threadIdx.x + l * 256;
            const int gj = base + tile + j;
            const float x = posb[gj * 3 + 0];
            const float y = posb[gj * 3 + 1];
            const float z = posb[gj * 3 + 2];
            sp[j] = make_float4(x, y, z, x * x + y * y + z * z);
        }
        __syncthreads();

#pragma unroll 4
        for (int j = 0; j < KNN_TILE; j++) {
            const float4 pj = sp[j];
            float dot = pix * pj.x;
            dot = fmaf(piy, pj.y, dot);
            dot = fmaf(piz, pj.z, dot);
            const float d2 = fmaf(-2.0f, dot, sqi + pj.w);
            if (d2 < d[0]) sorted_insert16(d, id, d2, base + tile + j);
        }
    }

    const size_t o = (((size_t)b * NN + i) * KNN_SPLIT + s) * KK;
#pragma unroll
    for (int t = 0; t < KK; t++) { g_knn_d[o + t] = d[t]; g_knn_i[o + t] = id[t]; }
}

// ---------------------------------------------------------------------------
// KNN pass B: one thread per query merges the 2x16 candidates into top-16.
// Half 0 (lower indices) scanned first -> lowest-index tie-break preserved.
// ---------------------------------------------------------------------------
__global__ void knn_merge() {
    const int q = blockIdx.x * blockDim.x + threadIdx.x;
    if (q >= MM) return;

    float d[KK];
    int   id[KK];
#pragma unroll
    for (int t = 0; t < KK; t++) { d[t] = 3.4e38f; id[t] = 0; }

    const size_t o = (size_t)q * KNN_SPLIT * KK;
    // each half's list is ascending from slot 15 down; scan all 32 entries
#pragma unroll
    for (int s = 0; s < KNN_SPLIT; s++) {
#pragma unroll
        for (int t = KK - 1; t >= 0; t--) {
            const float v = g_knn_d[o + s * KK + t];
            const int   j = g_knn_i[o + s * KK + t];
            if (v < d[0]) sorted_insert16(d, id, v, j);
        }
    }

    int* op = g_idx + (size_t)q * KK;
#pragma unroll
    for (int t = 0; t < KK; t++) op[t] = id[t];
}

// ---------------------------------------------------------------------------
// GEMM core: C[M,N] = A[M,128] @ W[128,N] (+ bias)
// BM=128, BN=128, BK=8, 256 threads, 8x8 micro-tile (4+4 split halves).
// ---------------------------------------------------------------------------
template <bool BIAS>
__device__ __forceinline__ void gemm_body(
    const float* __restrict__ A, const float* __restrict__ W,
    const float* __restrict__ bias, float* __restrict__ Cout,
    int N, int bm, int bn) {
    __shared__ float As[8][128];   // transposed A tile: As[k][m]
    __shared__ float Bs[8][128];   // W tile: Bs[k][n]

    const int tid = threadIdx.x;
    const int tx = tid & 15;    // 0..15 -> column groups
    const int ty = tid >> 4;    // 0..15 -> row groups

    float acc[8][8];
#pragma unroll
    for (int u = 0; u < 8; u++)
#pragma unroll
        for (int v = 0; v < 8; v++) acc[u][v] = 0.0f;

    const int ar = tid >> 1;            // A row 0..127
    const int ac4 = (tid & 1) * 4;      // A col 0 or 4
    const int wr = tid >> 5;            // W row 0..7
    const int wc = (tid & 31) * 4;      // W col 0..124

    for (int k0 = 0; k0 < 128; k0 += 8) {
        const float4 av = *(const float4*)&A[(size_t)(bm + ar) * 128 + k0 + ac4];
        const float4 wv = *(const float4*)&W[(size_t)(k0 + wr) * N + bn + wc];
        As[ac4 + 0][ar] = av.x;
        As[ac4 + 1][ar] = av.y;
        As[ac4 + 2][ar] = av.z;
        As[ac4 + 3][ar] = av.w;
        *(float4*)&Bs[wr][wc] = wv;
        __syncthreads();

#pragma unroll
        for (int kk = 0; kk < 8; kk++) {
            float a[8], bfr[8];
            *(float4*)&a[0]   = *(const float4*)&As[kk][ty * 4];
            *(float4*)&a[4]   = *(const float4*)&As[kk][64 + ty * 4];
            *(float4*)&bfr[0] = *(const float4*)&Bs[kk][tx * 4];
            *(float4*)&bfr[4] = *(const float4*)&Bs[kk][64 + tx * 4];
#pragma unroll
            for (int u = 0; u < 8; u++)
#pragma unroll
                for (int v = 0; v < 8; v++)
                    acc[u][v] = fmaf(a[u], bfr[v], acc[u][v]);
        }
        __syncthreads();
    }

#pragma unroll
    for (int hu = 0; hu < 2; hu++) {
#pragma unroll
        for (int u = 0; u < 4; u++) {
            const int row = bm + hu * 64 + ty * 4 + u;
            float* cp = &Cout[(size_t)row * N + bn];
#pragma unroll
            for (int hv = 0; hv < 2; hv++) {
                const int colb = hv * 64 + tx * 4;
                float4 r;
                r.x = acc[hu * 4 + u][hv * 4 + 0];
                r.y = acc[hu * 4 + u][hv * 4 + 1];
                r.z = acc[hu * 4 + u][hv * 4 + 2];
                r.w = acc[hu * 4 + u][hv * 4 + 3];
                if (BIAS) {
                    r.x += bias[bn + colb + 0];
                    r.y += bias[bn + colb + 1];
                    r.z += bias[bn + colb + 2];
                    r.w += bias[bn + colb + 3];
                }
                *(float4*)&cp[colb] = r;
            }
        }
    }
}

// Fused projections: z selects {W_src->g_asrc, W_dst->g_adst, W_val->g_v}
__global__ void __launch_bounds__(256, 2)
proj_kernel(const float* __restrict__ A,
            const float* __restrict__ Wsrc, const float* __restrict__ Wdst,
            const float* __restrict__ Wval,
            float* __restrict__ Osrc, float* __restrict__ Odst,
            float* __restrict__ Oval) {
    const float* W = (blockIdx.z == 0) ? Wsrc : (blockIdx.z == 1) ? Wdst : Wval;
    float* O       = (blockIdx.z == 0) ? Osrc : (blockIdx.z == 1) ? Odst : Oval;
    gemm_body<false>(A, W, nullptr, O, CC, blockIdx.x * 128, 0);
}

__global__ void __launch_bounds__(256, 2)
out_gemm_kernel(const float* __restrict__ A, const float* __restrict__ W,
                const float* __restrict__ bias, float* __restrict__ Cout) {
    gemm_body<true>(A, W, bias, Cout, HH, blockIdx.x * 128, blockIdx.y * 128);
}

// ---------------------------------------------------------------------------
// Attention: gather + per-(point,channel) softmax over 16 neighbors.
// One block (128 threads) per point; thread = channel. Softmax over the k
// axis is per-channel -> no cross-thread reduction at all.
// ---------------------------------------------------------------------------
__global__ void attn_kernel(const float* __restrict__ pos,
                            const float* __restrict__ Wpos,
                            const float* __restrict__ bpos) {
    const int b = blockIdx.y;
    const int i = blockIdx.x;
    const int c = threadIdx.x;

    __shared__ int   s_nbr[KK];
    __shared__ float s_rel[KK][3];

    const float* posb = pos + (size_t)b * NN * 3;
    if (c < KK) {
        const int j = g_idx[((size_t)b * NN + i) * KK + c];
        s_nbr[c] = j;
        s_rel[c][0] = posb[i * 3 + 0] - posb[j * 3 + 0];
        s_rel[c][1] = posb[i * 3 + 1] - posb[j * 3 + 1];
        s_rel[c][2] = posb[i * 3 + 2] - posb[j * 3 + 2];
    }
    __syncthreads();

    const float w0 = Wpos[c];
    const float w1 = Wpos[128 + c];
    const float w2 = Wpos[256 + c];
    const float bp = bpos[c];

    const float* asrc = g_asrc + (size_t)b * NN * CC;
    const float* vv   = g_v    + (size_t)b * NN * CC;
    const float adst  = g_adst[((size_t)b * NN + i) * CC + c];

    float alpha[KK], val[KK];
#pragma unroll
    for (int t = 0; t < KK; t++) {
        const int j = s_nbr[t];
        float delta = fmaf(s_rel[t][2], w2, bp);
        delta = fmaf(s_rel[t][1], w1, delta);
        delta = fmaf(s_rel[t][0], w0, delta);
        alpha[t] = adst - asrc[(size_t)j * CC + c] + delta;
        val[t]   = vv[(size_t)j * CC + c] + delta;
    }

    float m = alpha[0];
#pragma unroll
    for (int t = 1; t < KK; t++) m = fmaxf(m, alpha[t]);

    float s = 0.0f, acc = 0.0f;
#pragma unroll
    for (int t = 0; t < KK; t++) {
        const float e = expf(alpha[t] - m);
        s += e;
        acc = fmaf(e, val[t], acc);
    }
    g_acc[((size_t)b * NN + i) * CC + c] = acc / s;
}

// ---------------------------------------------------------------------------
// Launch
// ---------------------------------------------------------------------------
extern "C" void kernel_launch(void* const* d_in, const int* in_sizes, int n_in,
                              void* d_out, int out_size) {
    const float* x    = (const float*)d_in[0];
    const float* pos  = (const float*)d_in[1];
    const float* Wsrc = (const float*)d_in[2];
    const float* Wdst = (const float*)d_in[3];
    const float* Wval = (const float*)d_in[4];
    const float* Wpos = (const float*)d_in[5];
    const float* bpos = (const float*)d_in[6];
    const float* Wout = (const float*)d_in[7];
    const float* bout = (const float*)d_in[8];
    float* out = (float*)d_out;

    float *p_asrc, *p_adst, *p_v, *p_acc;
    cudaGetSymbolAddress((void**)&p_asrc, g_asrc);
    cudaGetSymbolAddress((void**)&p_adst, g_adst);
    cudaGetSymbolAddress((void**)&p_v,    g_v);
    cudaGetSymbolAddress((void**)&p_acc,  g_acc);

    // 1) KNN: split-scan then merge
    knn_pass_a<<<dim3(NN / 256, BB, KNN_SPLIT), 256>>>(pos);
    knn_merge<<<(MM + 255) / 256, 256>>>();

    // 2) projections: a_src, a_dst, v   (M=32768, K=128, N=128), fused over z
    proj_kernel<<<dim3(MM / 128, 1, 3), 256>>>(x, Wsrc, Wdst, Wval,
                                               p_asrc, p_adst, p_v);

    // 3) gather + softmax + weighted sum -> g_acc
    attn_kernel<<<dim3(NN, BB), 128>>>(pos, Wpos, bpos);

    // 4) output projection: out = g_acc @ W_out + b_out  (N=256)
    out_gemm_kernel<<<dim3(MM / 128, HH / 128), 256>>>(p_acc, Wout, bout, out);
}